// round 10
// baseline (speedup 1.0000x reference)
#include <cuda_runtime.h>
#include <cuda_fp16.h>

// Problem constants (fixed by the reference setup)
#define B_ 4
#define C_ 3
#define H_ 512
#define W_ 960
#define HW_ (H_ * W_)

// Tile geometry: 64x16 pixels per block, 256 threads, one 2x2 quad per thread
#define TW 64
#define TH 16
#define SWU (TW + 13)         // 77 used cols: halo 6 left, 7 right
#define PITCH 80              // row pitch in texels; 80 % 16 == 0 -> bank hash dy-invariant
#define SH (TH + 13)          // 29 rows: halo 6 top, 7 bottom
#define NTEX (SWU * SH)       // texels to stage

__global__ void __launch_bounds__(256, 4)
fi_quad_kernel(const float* __restrict__ inp,
               const float* __restrict__ flow,
               const float* __restrict__ filt,
               float* __restrict__ out)
{
    // one 8-byte texel per pixel: (half c0, half c1, half c2, 0)
    __shared__ uint2 sm[PITCH * SH];   // 18.6 KB

    const int x0 = blockIdx.x * TW;
    const int y0 = blockIdx.y * TH;
    const int b  = blockIdx.z;
    const int tid = threadIdx.x;

    const float* __restrict__ ibase = inp + (size_t)b * C_ * HW_;

    // ---- stage tile + halo into smem (border clamp baked in, fp32 -> fp16x3) ----
    #pragma unroll 3
    for (int idx = tid; idx < NTEX; idx += 256) {
        const int j = idx / SWU;
        const int i = idx - j * SWU;
        const int gy = min(max(y0 - 6 + j, 0), H_ - 1);
        const int gx = min(max(x0 - 6 + i, 0), W_ - 1);
        const int g  = gy * W_ + gx;
        const float v0 = ibase[g];
        const float v1 = ibase[g + HW_];
        const float v2 = ibase[g + 2 * HW_];
        __half2 h01 = __floats2half2_rn(v0, v1);
        __half2 h2p = __floats2half2_rn(v2, 0.0f);
        uint2 u;
        u.x = *reinterpret_cast<unsigned*>(&h01);
        u.y = *reinterpret_cast<unsigned*>(&h2p);
        sm[j * PITCH + i] = u;
    }
    __syncthreads();

    // quad layout: lane pair-x, warp covers 2 rows of the 64-wide tile
    const int xi    = x0 + (tid & 31) * 2;   // even x of the pair
    const int ybase = y0 + (tid >> 5) * 2;   // 8 warps * 2 rows = 16

    const float* __restrict__ flowx = flow + ((size_t)b * 2 + 0) * HW_;
    const float* __restrict__ flowy = flow + ((size_t)b * 2 + 1) * HW_;
    const float* __restrict__ fbb   = filt + (size_t)b * 16 * HW_;
    float* __restrict__ obb         = out  + (size_t)b * C_ * HW_;

    #pragma unroll
    for (int k = 0; k < 2; k++) {
        const int y    = ybase + k;
        const int pixL = y * W_ + xi;

        // paired loads: flow + 16 filter taps, one float2 each
        const float2 fxp = *reinterpret_cast<const float2*>(flowx + pixL);
        const float2 fyp = *reinterpret_cast<const float2*>(flowy + pixL);

        float2 f2[16];
        const float* fb = fbb + pixL;
        #pragma unroll
        for (int t = 0; t < 16; t++)
            f2[t] = *reinterpret_cast<const float2*>(fb + t * HW_);

        float res[2][3];

        #pragma unroll
        for (int s = 0; s < 2; s++) {
            const int   x   = xi + s;
            const float cfx = s ? fxp.y : fxp.x;
            const float cfy = s ? fyp.y : fyp.x;

            const float x2 = (float)x + cfx;
            const float y2 = (float)y + cfy;

            const bool valid =
                (x2 >= 0.0f) && (x2 <= (float)(W_ - 1)) &&
                (y2 >= 0.0f) && (y2 <= (float)(H_ - 1)) &&
                (fabsf(cfx) < (float)W_ * 0.5f) &&
                (fabsf(cfy) < (float)H_ * 0.5f);
            const float validf = valid ? 1.0f : 0.0f;

            const int   ix = __float2int_rd(x2);
            const int   iy = __float2int_rd(y2);
            const float a  = x2 - (float)ix;
            const float bt = y2 - (float)iy;

            const float wTL = (1.0f - a) * (1.0f - bt);
            const float wTR = a * (1.0f - bt);
            const float wBL = (1.0f - a) * bt;
            const float wBR = a * bt;

            // window coords, clamped into staged halo (branchless)
            const int ly  = iy - y0 + 5;
            const int lx  = ix - x0 + 5;
            const int lyc = min(max(ly, 0), SH - 5);
            const int lxc = min(max(lx, 0), SWU - 5);
            const bool fixup = valid && ((lyc != ly) || (lxc != lx));

            float r0 = 0.0f, r1 = 0.0f, r2 = 0.0f;

            // unconditional fast path: 25 taps, HFMA2 row accumulation
            {
                const uint2* s0 = sm + lyc * PITCH + lxc;
                #pragma unroll
                for (int r = 0; r < 5; r++) {
                    __half2 acc01 = __floats2half2_rn(0.0f, 0.0f);
                    __half2 acc2p = acc01;
                    #pragma unroll
                    for (int c = 0; c < 5; c++) {
                        float w = 0.0f;
                        #define FV(i_) (s ? f2[i_].y : f2[i_].x)
                        if (r < 4 && c < 4)  w += wTL * FV(r * 4 + c);
                        if (r < 4 && c >= 1) w += wTR * FV(r * 4 + c - 1);
                        if (r >= 1 && c < 4) w += wBL * FV((r - 1) * 4 + c);
                        if (r >= 1 && c >= 1)w += wBR * FV((r - 1) * 4 + c - 1);
                        #undef FV

                        const uint2 u = s0[r * PITCH + c];
                        const __half2 h01 = *reinterpret_cast<const __half2*>(&u.x);
                        const __half2 h2p = *reinterpret_cast<const __half2*>(&u.y);
                        const __half2 w2  = __float2half2_rn(w);
                        acc01 = __hfma2(w2, h01, acc01);
                        acc2p = __hfma2(w2, h2p, acc2p);
                    }
                    const float2 p01 = __half22float2(acc01);
                    r0 += p01.x;
                    r1 += p01.y;
                    r2 += __low2float(acc2p);
                }
            }

            // rare fix-up (warp-uniformly skipped ~always): global gathers
            if (__any_sync(0xffffffffu, fixup)) {
                if (fixup) {
                    r0 = 0.0f; r1 = 0.0f; r2 = 0.0f;
                    #pragma unroll 1
                    for (int r = 0; r < 5; r++) {
                        const int yy = min(max(iy - 1 + r, 0), H_ - 1);
                        const float* g0 = ibase + yy * W_;
                        #pragma unroll 1
                        for (int c = 0; c < 5; c++) {
                            float w = 0.0f;
                            #define FV(i_) (s ? f2[i_].y : f2[i_].x)
                            if (r < 4 && c < 4)  w += wTL * FV(r * 4 + c);
                            if (r < 4 && c >= 1) w += wTR * FV(r * 4 + c - 1);
                            if (r >= 1 && c < 4) w += wBL * FV((r - 1) * 4 + c);
                            if (r >= 1 && c >= 1)w += wBR * FV((r - 1) * 4 + c - 1);
                            #undef FV

                            const int xo = min(max(ix - 1 + c, 0), W_ - 1);
                            r0 += w * __ldg(g0 + xo);
                            r1 += w * __ldg(g0 + xo + HW_);
                            r2 += w * __ldg(g0 + xo + 2 * HW_);
                        }
                    }
                }
            }

            res[s][0] = r0 * validf;
            res[s][1] = r1 * validf;
            res[s][2] = r2 * validf;
        }

        // paired stores: one STG.64 per channel
        float* ob = obb + pixL;
        *reinterpret_cast<float2*>(ob)            = make_float2(res[0][0], res[1][0]);
        *reinterpret_cast<float2*>(ob + HW_)      = make_float2(res[0][1], res[1][1]);
        *reinterpret_cast<float2*>(ob + 2 * HW_)  = make_float2(res[0][2], res[1][2]);
    }
}

extern "C" void kernel_launch(void* const* d_in, const int* in_sizes, int n_in,
                              void* d_out, int out_size)
{
    const float* teninput  = (const float*)d_in[0];
    const float* tenflow   = (const float*)d_in[1];
    const float* tenfilter = (const float*)d_in[2];
    float* out = (float*)d_out;

    dim3 grid(W_ / TW, H_ / TH, B_);   // 15 x 32 x 4
    fi_quad_kernel<<<grid, 256>>>(teninput, tenflow, tenfilter, out);
}

// round 11
// speedup vs baseline: 1.0314x; 1.0314x over previous
#include <cuda_runtime.h>
#include <cuda_fp16.h>

// Problem constants (fixed by the reference setup)
#define B_ 4
#define C_ 3
#define H_ 512
#define W_ 960
#define HW_ (H_ * W_)

// Tile geometry: 64x32 pixels per block, 512 threads, 4 pixels/thread (along y)
#define TW 64
#define TH 32
#define NTHREADS 512
#define SWU (TW + 13)         // 77 used cols: halo 6 left, 7 right
#define PITCH 80              // row pitch in texels; 80 % 16 == 0 -> bank hash dy-invariant
#define SH (TH + 13)          // 45 rows: halo 6 top, 7 bottom
#define NTEX (SWU * SH)       // 3465 texels to stage

__global__ void __launch_bounds__(NTHREADS, 3)
fi_tiled_h11_kernel(const float* __restrict__ inp,
                    const float* __restrict__ flow,
                    const float* __restrict__ filt,
                    float* __restrict__ out)
{
    // one 8-byte texel per pixel: (half c0, half c1, half c2, 0)
    __shared__ uint2 sm[PITCH * SH];   // 28.8 KB

    const int x0 = blockIdx.x * TW;
    const int y0 = blockIdx.y * TH;
    const int b  = blockIdx.z;
    const int tid = threadIdx.x;

    const float* __restrict__ ibase = inp + (size_t)b * C_ * HW_;

    // ---- stage tile + halo into smem (border clamp baked in, fp32 -> fp16x3) ----
    #pragma unroll 3
    for (int idx = tid; idx < NTEX; idx += NTHREADS) {
        const int j = idx / SWU;
        const int i = idx - j * SWU;
        const int gy = min(max(y0 - 6 + j, 0), H_ - 1);
        const int gx = min(max(x0 - 6 + i, 0), W_ - 1);
        const int g  = gy * W_ + gx;
        const float v0 = ibase[g];
        const float v1 = ibase[g + HW_];
        const float v2 = ibase[g + 2 * HW_];
        __half2 h01 = __floats2half2_rn(v0, v1);
        __half2 h2p = __floats2half2_rn(v2, 0.0f);
        uint2 u;
        u.x = *reinterpret_cast<unsigned*>(&h01);
        u.y = *reinterpret_cast<unsigned*>(&h2p);
        sm[j * PITCH + i] = u;
    }
    __syncthreads();

    const int x     = x0 + (tid & 63);
    const int tyg   = tid >> 6;            // 0..7
    const int ybase = y0 + tyg * 4;

    const float* __restrict__ flowx = flow + ((size_t)b * 2 + 0) * HW_;
    const float* __restrict__ flowy = flow + ((size_t)b * 2 + 1) * HW_;
    const float* __restrict__ fbb   = filt + (size_t)b * 16 * HW_;
    float* __restrict__ obb         = out  + (size_t)b * C_ * HW_;

    // ---- hoist ALL flow loads: 8 independent LDGs in flight up-front ----
    float fxv[4], fyv[4];
    #pragma unroll
    for (int k = 0; k < 4; k++) {
        fxv[k] = __ldcs(flowx + (ybase + k) * W_ + x);
        fyv[k] = __ldcs(flowy + (ybase + k) * W_ + x);
    }

    #pragma unroll
    for (int k = 0; k < 4; k++) {
        const int y   = ybase + k;
        const int pix = y * W_ + x;

        const float cfx = fxv[k], cfy = fyv[k];
        const float x2 = (float)x + cfx;
        const float y2 = (float)y + cfy;

        const bool valid =
            (x2 >= 0.0f) && (x2 <= (float)(W_ - 1)) &&
            (y2 >= 0.0f) && (y2 <= (float)(H_ - 1)) &&
            (fabsf(cfx) < (float)W_ * 0.5f) &&
            (fabsf(cfy) < (float)H_ * 0.5f);
        const float validf = valid ? 1.0f : 0.0f;

        const int   ix = __float2int_rd(x2);
        const int   iy = __float2int_rd(y2);
        const float a  = x2 - (float)ix;
        const float bt = y2 - (float)iy;

        const float wTL = (1.0f - a) * (1.0f - bt);
        const float wTR = a * (1.0f - bt);
        const float wBL = (1.0f - a) * bt;
        const float wBR = a * bt;

        // ---- preload 16 filter taps (wide MLP; streaming read-once) ----
        float f[16];
        const float* fb = fbb + pix;
        #pragma unroll
        for (int t = 0; t < 16; t++) f[t] = __ldcs(fb + t * HW_);

        // ---- window coords, clamped into the staged halo (branchless) ----
        const int ly  = iy - y0 + 5;
        const int lx  = ix - x0 + 5;
        const int lyc = min(max(ly, 0), SH - 5);
        const int lxc = min(max(lx, 0), SWU - 5);
        const bool fixup = valid && ((lyc != ly) || (lxc != lx));

        float r0 = 0.0f, r1 = 0.0f, r2 = 0.0f;

        // ---- unconditional fast path: 25 taps, HFMA2 row accumulation ----
        {
            const uint2* s0 = sm + lyc * PITCH + lxc;
            #pragma unroll
            for (int r = 0; r < 5; r++) {
                __half2 acc01 = __floats2half2_rn(0.0f, 0.0f);
                __half2 acc2p = acc01;
                #pragma unroll
                for (int c = 0; c < 5; c++) {
                    float w = 0.0f;
                    if (r < 4 && c < 4)  w += wTL * f[r * 4 + c];
                    if (r < 4 && c >= 1) w += wTR * f[r * 4 + c - 1];
                    if (r >= 1 && c < 4) w += wBL * f[(r - 1) * 4 + c];
                    if (r >= 1 && c >= 1)w += wBR * f[(r - 1) * 4 + c - 1];

                    const uint2 u = s0[r * PITCH + c];
                    const __half2 h01 = *reinterpret_cast<const __half2*>(&u.x);
                    const __half2 h2p = *reinterpret_cast<const __half2*>(&u.y);
                    const __half2 w2  = __float2half2_rn(w);
                    acc01 = __hfma2(w2, h01, acc01);
                    acc2p = __hfma2(w2, h2p, acc2p);
                }
                const float2 p01 = __half22float2(acc01);
                r0 += p01.x;
                r1 += p01.y;
                r2 += __low2float(acc2p);
            }
        }

        // ---- rare fix-up (warp-uniformly skipped ~always): global gathers ----
        if (__any_sync(0xffffffffu, fixup)) {
            if (fixup) {
                r0 = 0.0f; r1 = 0.0f; r2 = 0.0f;
                #pragma unroll 1
                for (int r = 0; r < 5; r++) {
                    const int yy = min(max(iy - 1 + r, 0), H_ - 1);
                    const float* g0 = ibase + yy * W_;
                    #pragma unroll 1
                    for (int c = 0; c < 5; c++) {
                        float w = 0.0f;
                        if (r < 4 && c < 4)  w += wTL * f[r * 4 + c];
                        if (r < 4 && c >= 1) w += wTR * f[r * 4 + c - 1];
                        if (r >= 1 && c < 4) w += wBL * f[(r - 1) * 4 + c];
                        if (r >= 1 && c >= 1)w += wBR * f[(r - 1) * 4 + c - 1];

                        const int xo = min(max(ix - 1 + c, 0), W_ - 1);
                        r0 += w * __ldg(g0 + xo);
                        r1 += w * __ldg(g0 + xo + HW_);
                        r2 += w * __ldg(g0 + xo + 2 * HW_);
                    }
                }
            }
        }

        float* ob = obb + pix;
        ob[0]       = r0 * validf;
        ob[HW_]     = r1 * validf;
        ob[2 * HW_] = r2 * validf;
    }
}

extern "C" void kernel_launch(void* const* d_in, const int* in_sizes, int n_in,
                              void* d_out, int out_size)
{
    const float* teninput  = (const float*)d_in[0];
    const float* tenflow   = (const float*)d_in[1];
    const float* tenfilter = (const float*)d_in[2];
    float* out = (float*)d_out;

    dim3 grid(W_ / TW, H_ / TH, B_);   // 15 x 16 x 4
    fi_tiled_h11_kernel<<<grid, NTHREADS>>>(teninput, tenflow, tenfilter, out);
}

// round 12
// speedup vs baseline: 1.0755x; 1.0428x over previous
#include <cuda_runtime.h>
#include <cuda_fp16.h>

// Problem constants (fixed by the reference setup)
#define B_ 4
#define C_ 3
#define H_ 512
#define W_ 960
#define HW_ (H_ * W_)

// Tile geometry: 64x16 pixels per block, 256 threads, 4 pixels/thread (along y)
#define TW 64
#define TH 16
#define NTHREADS 256
#define SWU (TW + 13)         // 77 used cols: halo 6 left, 7 right
#define PITCH 80              // row pitch in texels; 80 % 16 == 0 -> bank hash dy-invariant
#define SH (TH + 13)          // 29 rows: halo 6 top, 7 bottom
#define NTEX (SWU * SH)       // texels to stage

__global__ void __launch_bounds__(NTHREADS, 5)
fi_tiled_h12_kernel(const float* __restrict__ inp,
                    const float* __restrict__ flow,
                    const float* __restrict__ filt,
                    float* __restrict__ out)
{
    // one 8-byte texel per pixel: (half c0, half c1, half c2, 0)
    __shared__ uint2 sm[PITCH * SH];   // 18.6 KB

    const int x0 = blockIdx.x * TW;
    const int y0 = blockIdx.y * TH;
    const int b  = blockIdx.z;
    const int tid = threadIdx.x;

    const float* __restrict__ ibase = inp + (size_t)b * C_ * HW_;

    // ---- stage tile + halo into smem (border clamp baked in, fp32 -> fp16x3) ----
    #pragma unroll 3
    for (int idx = tid; idx < NTEX; idx += NTHREADS) {
        const int j = idx / SWU;
        const int i = idx - j * SWU;
        const int gy = min(max(y0 - 6 + j, 0), H_ - 1);
        const int gx = min(max(x0 - 6 + i, 0), W_ - 1);
        const int g  = gy * W_ + gx;
        const float v0 = ibase[g];
        const float v1 = ibase[g + HW_];
        const float v2 = ibase[g + 2 * HW_];
        __half2 h01 = __floats2half2_rn(v0, v1);
        __half2 h2p = __floats2half2_rn(v2, 0.0f);
        uint2 u;
        u.x = *reinterpret_cast<unsigned*>(&h01);
        u.y = *reinterpret_cast<unsigned*>(&h2p);
        sm[j * PITCH + i] = u;
    }
    __syncthreads();

    const int x     = x0 + (tid & 63);
    const int tyg   = tid >> 6;            // 0..3
    const int ybase = y0 + tyg * 4;

    const float* __restrict__ flowx = flow + ((size_t)b * 2 + 0) * HW_;
    const float* __restrict__ flowy = flow + ((size_t)b * 2 + 1) * HW_;
    const float* __restrict__ fbb   = filt + (size_t)b * 16 * HW_;
    float* __restrict__ obb         = out  + (size_t)b * C_ * HW_;

    // ---- hoist ALL flow loads: 8 independent LDGs in flight up-front ----
    float fxv[4], fyv[4];
    #pragma unroll
    for (int k = 0; k < 4; k++) {
        fxv[k] = __ldcs(flowx + (ybase + k) * W_ + x);
        fyv[k] = __ldcs(flowy + (ybase + k) * W_ + x);
    }

    #pragma unroll
    for (int k = 0; k < 4; k++) {
        const int y   = ybase + k;
        const int pix = y * W_ + x;

        const float cfx = fxv[k], cfy = fyv[k];
        const float x2 = (float)x + cfx;
        const float y2 = (float)y + cfy;

        const bool valid =
            (x2 >= 0.0f) && (x2 <= (float)(W_ - 1)) &&
            (y2 >= 0.0f) && (y2 <= (float)(H_ - 1)) &&
            (fabsf(cfx) < (float)W_ * 0.5f) &&
            (fabsf(cfy) < (float)H_ * 0.5f);
        const float validf = valid ? 1.0f : 0.0f;

        const int   ix = __float2int_rd(x2);
        const int   iy = __float2int_rd(y2);
        const float a  = x2 - (float)ix;
        const float bt = y2 - (float)iy;

        const float wTL = (1.0f - a) * (1.0f - bt);
        const float wTR = a * (1.0f - bt);
        const float wBL = (1.0f - a) * bt;
        const float wBR = a * bt;

        // ---- preload 16 filter taps (wide MLP; streaming read-once) ----
        float f[16];
        const float* fb = fbb + pix;
        #pragma unroll
        for (int t = 0; t < 16; t++) f[t] = __ldcs(fb + t * HW_);

        // ---- window coords, clamped into the staged halo (branchless) ----
        const int ly  = iy - y0 + 5;
        const int lx  = ix - x0 + 5;
        const int lyc = min(max(ly, 0), SH - 5);
        const int lxc = min(max(lx, 0), SWU - 5);
        const bool fixup = valid && ((lyc != ly) || (lxc != lx));

        float r0 = 0.0f, r1 = 0.0f, r2 = 0.0f;

        // ---- fast path: 25 taps, software-pipelined by row.
        //      Row r+1's 5 LDS are issued BEFORE row r's math consumes cur[]. ----
        {
            const uint2* s0 = sm + lyc * PITCH + lxc;

            uint2 cur[5], nxt[5];
            #pragma unroll
            for (int c = 0; c < 5; c++) cur[c] = s0[c];

            #pragma unroll
            for (int r = 0; r < 5; r++) {
                if (r < 4) {
                    const uint2* sr = s0 + (r + 1) * PITCH;
                    #pragma unroll
                    for (int c = 0; c < 5; c++) nxt[c] = sr[c];
                }

                __half2 acc01 = __floats2half2_rn(0.0f, 0.0f);
                __half2 acc2p = acc01;
                #pragma unroll
                for (int c = 0; c < 5; c++) {
                    float w = 0.0f;
                    if (r < 4 && c < 4)  w += wTL * f[r * 4 + c];
                    if (r < 4 && c >= 1) w += wTR * f[r * 4 + c - 1];
                    if (r >= 1 && c < 4) w += wBL * f[(r - 1) * 4 + c];
                    if (r >= 1 && c >= 1)w += wBR * f[(r - 1) * 4 + c - 1];

                    const uint2 u = cur[c];
                    const __half2 h01 = *reinterpret_cast<const __half2*>(&u.x);
                    const __half2 h2p = *reinterpret_cast<const __half2*>(&u.y);
                    const __half2 w2  = __float2half2_rn(w);
                    acc01 = __hfma2(w2, h01, acc01);
                    acc2p = __hfma2(w2, h2p, acc2p);
                }
                const float2 p01 = __half22float2(acc01);
                r0 += p01.x;
                r1 += p01.y;
                r2 += __low2float(acc2p);

                if (r < 4) {
                    #pragma unroll
                    for (int c = 0; c < 5; c++) cur[c] = nxt[c];
                }
            }
        }

        // ---- rare fix-up (warp-uniformly skipped ~always): global gathers ----
        if (__any_sync(0xffffffffu, fixup)) {
            if (fixup) {
                r0 = 0.0f; r1 = 0.0f; r2 = 0.0f;
                #pragma unroll 1
                for (int r = 0; r < 5; r++) {
                    const int yy = min(max(iy - 1 + r, 0), H_ - 1);
                    const float* g0 = ibase + yy * W_;
                    #pragma unroll 1
                    for (int c = 0; c < 5; c++) {
                        float w = 0.0f;
                        if (r < 4 && c < 4)  w += wTL * f[r * 4 + c];
                        if (r < 4 && c >= 1) w += wTR * f[r * 4 + c - 1];
                        if (r >= 1 && c < 4) w += wBL * f[(r - 1) * 4 + c];
                        if (r >= 1 && c >= 1)w += wBR * f[(r - 1) * 4 + c - 1];

                        const int xo = min(max(ix - 1 + c, 0), W_ - 1);
                        r0 += w * __ldg(g0 + xo);
                        r1 += w * __ldg(g0 + xo + HW_);
                        r2 += w * __ldg(g0 + xo + 2 * HW_);
                    }
                }
            }
        }

        float* ob = obb + pix;
        ob[0]       = r0 * validf;
        ob[HW_]     = r1 * validf;
        ob[2 * HW_] = r2 * validf;
    }
}

extern "C" void kernel_launch(void* const* d_in, const int* in_sizes, int n_in,
                              void* d_out, int out_size)
{
    const float* teninput  = (const float*)d_in[0];
    const float* tenflow   = (const float*)d_in[1];
    const float* tenfilter = (const float*)d_in[2];
    float* out = (float*)d_out;

    dim3 grid(W_ / TW, H_ / TH, B_);   // 15 x 32 x 4
    fi_tiled_h12_kernel<<<grid, NTHREADS>>>(teninput, tenflow, tenfilter, out);
}